// round 3
// baseline (speedup 1.0000x reference)
#include <cuda_runtime.h>
#include <math.h>

#define B_  8
#define S_  2048
#define D_  64
#define BM  64      // q rows per block
#define BN  64      // kv rows per tile
#define CH  16      // keys per softmax chunk

// One q-row per THREAD PAIR: thread (2r+h) owns half h (32 floats) of row r's
// query/accumulator. Score = partial dot + one shfl.bfly. 128 threads = 4 warps
// per block; allow 2 blocks/SM for latency hiding (2 warps/SMSP).
__global__ __launch_bounds__(128, 2) void fa_fp32(
    const float* __restrict__ Q, const float* __restrict__ K,
    const float* __restrict__ V, float* __restrict__ O)
{
    __shared__ float4 Ks[BN * (D_ / 4)];
    __shared__ float4 Vs[BN * (D_ / 4)];

    const int qi  = blockIdx.x;     // q tile index
    const int b   = blockIdx.y;     // batch
    const int tid = threadIdx.x;
    const int r   = tid >> 1;       // row within q tile
    const int h   = tid & 1;        // which half of D this thread owns
    const int row = qi * BM + r;    // global q row

    // Load this thread's half-query into registers (8 x float4 = 32 floats)
    const float4* qptr = (const float4*)(Q + ((size_t)(b * S_ + row)) * D_ + h * 32);
    float4 q[8];
#pragma unroll
    for (int i = 0; i < 8; i++) q[i] = qptr[i];

    float4 acc[8];
#pragma unroll
    for (int i = 0; i < 8; i++) acc[i] = make_float4(0.f, 0.f, 0.f, 0.f);
    float m = -INFINITY;   // running max
    float l = 0.f;         // running denom

    const int ntiles = qi + 1;      // causal: only tiles 0..qi needed
    for (int t = 0; t < ntiles; t++) {
        const float4* kp = (const float4*)(K + ((size_t)(b * S_ + t * BN)) * D_);
        const float4* vp = (const float4*)(V + ((size_t)(b * S_ + t * BN)) * D_);
        __syncthreads();
#pragma unroll
        for (int i = 0; i < (BN * D_ / 4) / 128; i++) {   // 8 float4 per thread
            int idx = i * 128 + tid;
            Ks[idx] = kp[idx];
            Vs[idx] = vp[idx];
        }
        __syncthreads();

        const int k0t = t * BN;
        for (int c = 0; c < BN / CH; c++) {
            // ---- scores for CH keys ----
            float s[CH];
#pragma unroll
            for (int j = 0; j < CH; j++) {
                const float4* krow = &Ks[(c * CH + j) * (D_ / 4) + h * 8];
                float sj = 0.f;
#pragma unroll
                for (int d4 = 0; d4 < 8; d4++) {
                    float4 kv = krow[d4];
                    sj = fmaf(q[d4].x, kv.x, sj);
                    sj = fmaf(q[d4].y, kv.y, sj);
                    sj = fmaf(q[d4].z, kv.z, sj);
                    sj = fmaf(q[d4].w, kv.w, sj);
                }
                // combine the two half-dots (partner lane differs only in h)
                sj += __shfl_xor_sync(0xffffffffu, sj, 1);
                s[j] = (k0t + c * CH + j <= row) ? sj : -INFINITY;
            }
            // ---- online softmax update ----
            float mt = m;
#pragma unroll
            for (int j = 0; j < CH; j++) mt = fmaxf(mt, s[j]);
            float scale = __expf(m - mt);   // 0 when m == -inf and mt finite
            m = mt;
            l *= scale;
#pragma unroll
            for (int i = 0; i < 8; i++) {
                acc[i].x *= scale; acc[i].y *= scale;
                acc[i].z *= scale; acc[i].w *= scale;
            }
#pragma unroll
            for (int j = 0; j < CH; j++) {
                float p = __expf(s[j] - m);  // 0 for masked keys
                l += p;
                const float4* vrow = &Vs[(c * CH + j) * (D_ / 4) + h * 8];
#pragma unroll
                for (int d4 = 0; d4 < 8; d4++) {
                    float4 vv = vrow[d4];
                    acc[d4].x = fmaf(p, vv.x, acc[d4].x);
                    acc[d4].y = fmaf(p, vv.y, acc[d4].y);
                    acc[d4].z = fmaf(p, vv.z, acc[d4].z);
                    acc[d4].w = fmaf(p, vv.w, acc[d4].w);
                }
            }
        }
    }

    const float inv = 1.f / l;
    float4* op = (float4*)(O + ((size_t)(b * S_ + row)) * D_ + h * 32);
#pragma unroll
    for (int i = 0; i < 8; i++) {
        float4 o = acc[i];
        o.x *= inv; o.y *= inv; o.z *= inv; o.w *= inv;
        op[i] = o;
    }
}

extern "C" void kernel_launch(void* const* d_in, const int* in_sizes, int n_in,
                              void* d_out, int out_size) {
    const float* q = (const float*)d_in[0];
    const float* k = (const float*)d_in[1];
    const float* v = (const float*)d_in[2];
    float* o = (float*)d_out;
    dim3 grid(S_ / BM, B_);   // 32 q-tiles x 8 batches = 256 blocks
    fa_fp32<<<grid, 128>>>(q, k, v, o);
}

// round 4
// speedup vs baseline: 2.6149x; 2.6149x over previous
#include <cuda_runtime.h>
#include <math.h>

#define B_   8
#define S_   2048
#define D_   64
#define BM   64
#define BN   64
#define NT   256
#define NTILES (S_ / BM)   // 32

// Register-tiled causal flash attention, fp32.
// Thread grid 32(ty) x 8(tx): thread owns rows {2ty,2ty+1} x cols {8tx..8tx+7}
// of both the 64x64 score tile and the 64x64 output tile.
// Block processes q-tile pair (31-bx, bx) -> exactly 33 kv tiles per block.
__global__ __launch_bounds__(NT, 2) void fa_reg(
    const float* __restrict__ Q, const float* __restrict__ K,
    const float* __restrict__ V, float* __restrict__ O)
{
    __shared__ float Qt[D_ * BM];     // [d][row]
    __shared__ float KtPt[D_ * BN];   // scores phase: Kt[d][key]; then Pt[key][row]
    __shared__ float Vs[BN * D_];     // [key][d]

    const int tid = threadIdx.x;
    const int tx  = tid & 7;
    const int ty  = tid >> 3;
    const int r0  = 2 * ty;
    const int r1  = r0 + 1;
    const int b   = blockIdx.y;

    const int ldrow = tid & 63;            // row/key handled in global loads
    const int lddb  = (tid >> 6) * 16;     // d-chunk base (4 groups x 16 dims)

    for (int pm = 0; pm < 2; pm++) {
        const int qi = pm ? blockIdx.x : (NTILES - 1 - blockIdx.x);

        __syncthreads();
        // ---- load Q tile transposed: Qt[d][row] ----
        {
            const float4* src = (const float4*)(Q + ((size_t)(b * S_ + qi * BM + ldrow)) * D_ + lddb);
#pragma unroll
            for (int j = 0; j < 4; j++) {
                float4 x = src[j];
                Qt[(lddb + 4*j + 0) * BM + ldrow] = x.x;
                Qt[(lddb + 4*j + 1) * BM + ldrow] = x.y;
                Qt[(lddb + 4*j + 2) * BM + ldrow] = x.z;
                Qt[(lddb + 4*j + 3) * BM + ldrow] = x.w;
            }
        }

        float o0[8], o1[8];
#pragma unroll
        for (int j = 0; j < 8; j++) { o0[j] = 0.f; o1[j] = 0.f; }
        float m0 = -INFINITY, m1 = -INFINITY;
        float l0 = 0.f, l1 = 0.f;

        for (int t = 0; t <= qi; t++) {
            __syncthreads();   // S1: prev PV done with Pt/Vs
            // ---- load K transposed + V straight ----
            {
                const float4* ksrc = (const float4*)(K + ((size_t)(b * S_ + t * BN + ldrow)) * D_ + lddb);
#pragma unroll
                for (int j = 0; j < 4; j++) {
                    float4 x = ksrc[j];
                    KtPt[(lddb + 4*j + 0) * BN + ldrow] = x.x;
                    KtPt[(lddb + 4*j + 1) * BN + ldrow] = x.y;
                    KtPt[(lddb + 4*j + 2) * BN + ldrow] = x.z;
                    KtPt[(lddb + 4*j + 3) * BN + ldrow] = x.w;
                }
                const float4* vsrc = (const float4*)(V + ((size_t)(b * S_ + t * BN)) * D_);
                float4* vdst = (float4*)Vs;
#pragma unroll
                for (int j = 0; j < 4; j++) vdst[tid + j * NT] = vsrc[tid + j * NT];
            }
            __syncthreads();   // S2: tiles visible

            // ---- scores: S[2x8] += q[r,d] * k[key,d] ----
            float s0[8], s1[8];
#pragma unroll
            for (int j = 0; j < 8; j++) { s0[j] = 0.f; s1[j] = 0.f; }
#pragma unroll 8
            for (int d = 0; d < D_; d++) {
                float q0 = Qt[d * BM + r0];
                float q1 = Qt[d * BM + r1];
                const float4* kp = (const float4*)&KtPt[d * BN + tx * 8];
                float4 ka = kp[0], kb = kp[1];
                s0[0] = fmaf(q0, ka.x, s0[0]); s0[1] = fmaf(q0, ka.y, s0[1]);
                s0[2] = fmaf(q0, ka.z, s0[2]); s0[3] = fmaf(q0, ka.w, s0[3]);
                s0[4] = fmaf(q0, kb.x, s0[4]); s0[5] = fmaf(q0, kb.y, s0[5]);
                s0[6] = fmaf(q0, kb.z, s0[6]); s0[7] = fmaf(q0, kb.w, s0[7]);
                s1[0] = fmaf(q1, ka.x, s1[0]); s1[1] = fmaf(q1, ka.y, s1[1]);
                s1[2] = fmaf(q1, ka.z, s1[2]); s1[3] = fmaf(q1, ka.w, s1[3]);
                s1[4] = fmaf(q1, kb.x, s1[4]); s1[5] = fmaf(q1, kb.y, s1[5]);
                s1[6] = fmaf(q1, kb.z, s1[6]); s1[7] = fmaf(q1, kb.w, s1[7]);
            }
            if (t == qi) {   // diagonal tile: causal mask (BM==BN so local compare)
                const int kb0 = tx * 8;
#pragma unroll
                for (int j = 0; j < 8; j++) {
                    if (kb0 + j > r0) s0[j] = -INFINITY;
                    if (kb0 + j > r1) s1[j] = -INFINITY;
                }
            }
            __syncthreads();   // S3: all Kt reads done (Pt will overwrite)

            // ---- online softmax (rows replicated across the 8 tx lanes) ----
            float a0 = fmaxf(fmaxf(fmaxf(s0[0], s0[1]), fmaxf(s0[2], s0[3])),
                             fmaxf(fmaxf(s0[4], s0[5]), fmaxf(s0[6], s0[7])));
            float a1 = fmaxf(fmaxf(fmaxf(s1[0], s1[1]), fmaxf(s1[2], s1[3])),
                             fmaxf(fmaxf(s1[4], s1[5]), fmaxf(s1[6], s1[7])));
            a0 = fmaxf(a0, __shfl_xor_sync(0xffffffffu, a0, 1));
            a0 = fmaxf(a0, __shfl_xor_sync(0xffffffffu, a0, 2));
            a0 = fmaxf(a0, __shfl_xor_sync(0xffffffffu, a0, 4));
            a1 = fmaxf(a1, __shfl_xor_sync(0xffffffffu, a1, 1));
            a1 = fmaxf(a1, __shfl_xor_sync(0xffffffffu, a1, 2));
            a1 = fmaxf(a1, __shfl_xor_sync(0xffffffffu, a1, 4));
            float mt0 = fmaxf(m0, a0), mt1 = fmaxf(m1, a1);
            float sc0 = __expf(m0 - mt0), sc1 = __expf(m1 - mt1);
            m0 = mt0; m1 = mt1;
            float ls0 = 0.f, ls1 = 0.f;
#pragma unroll
            for (int j = 0; j < 8; j++) {
                s0[j] = __expf(s0[j] - m0); ls0 += s0[j];
                s1[j] = __expf(s1[j] - m1); ls1 += s1[j];
            }
            ls0 += __shfl_xor_sync(0xffffffffu, ls0, 1);
            ls0 += __shfl_xor_sync(0xffffffffu, ls0, 2);
            ls0 += __shfl_xor_sync(0xffffffffu, ls0, 4);
            ls1 += __shfl_xor_sync(0xffffffffu, ls1, 1);
            ls1 += __shfl_xor_sync(0xffffffffu, ls1, 2);
            ls1 += __shfl_xor_sync(0xffffffffu, ls1, 4);
            l0 = l0 * sc0 + ls0;
            l1 = l1 * sc1 + ls1;
#pragma unroll
            for (int j = 0; j < 8; j++) { o0[j] *= sc0; o1[j] *= sc1; }

            // ---- write P key-major: Pt[key][row] (overwrites Kt) ----
#pragma unroll
            for (int j = 0; j < 8; j++) {
                KtPt[(tx * 8 + j) * BN + r0] = s0[j];
                KtPt[(tx * 8 + j) * BN + r1] = s1[j];
            }
            __syncthreads();   // S4: Pt visible

            // ---- PV: O[2x8] += P[r,k] * V[k,d] ----
#pragma unroll 8
            for (int k = 0; k < BN; k++) {
                float p0 = KtPt[k * BN + r0];
                float p1 = KtPt[k * BN + r1];
                const float4* vp = (const float4*)&Vs[k * D_ + tx * 8];
                float4 va = vp[0], vb = vp[1];
                o0[0] = fmaf(p0, va.x, o0[0]); o0[1] = fmaf(p0, va.y, o0[1]);
                o0[2] = fmaf(p0, va.z, o0[2]); o0[3] = fmaf(p0, va.w, o0[3]);
                o0[4] = fmaf(p0, vb.x, o0[4]); o0[5] = fmaf(p0, vb.y, o0[5]);
                o0[6] = fmaf(p0, vb.z, o0[6]); o0[7] = fmaf(p0, vb.w, o0[7]);
                o1[0] = fmaf(p1, va.x, o1[0]); o1[1] = fmaf(p1, va.y, o1[1]);
                o1[2] = fmaf(p1, va.z, o1[2]); o1[3] = fmaf(p1, va.w, o1[3]);
                o1[4] = fmaf(p1, vb.x, o1[4]); o1[5] = fmaf(p1, vb.y, o1[5]);
                o1[6] = fmaf(p1, vb.z, o1[6]); o1[7] = fmaf(p1, vb.w, o1[7]);
            }
        }

        // ---- epilogue ----
        const float inv0 = 1.f / l0, inv1 = 1.f / l1;
        float* og = O + ((size_t)(b * S_ + qi * BM)) * D_;
        float4 w;
        w = make_float4(o0[0]*inv0, o0[1]*inv0, o0[2]*inv0, o0[3]*inv0);
        *(float4*)(og + r0 * D_ + tx * 8) = w;
        w = make_float4(o0[4]*inv0, o0[5]*inv0, o0[6]*inv0, o0[7]*inv0);
        *(float4*)(og + r0 * D_ + tx * 8 + 4) = w;
        w = make_float4(o1[0]*inv1, o1[1]*inv1, o1[2]*inv1, o1[3]*inv1);
        *(float4*)(og + r1 * D_ + tx * 8) = w;
        w = make_float4(o1[4]*inv1, o1[5]*inv1, o1[6]*inv1, o1[7]*inv1);
        *(float4*)(og + r1 * D_ + tx * 8 + 4) = w;
    }
}

extern "C" void kernel_launch(void* const* d_in, const int* in_sizes, int n_in,
                              void* d_out, int out_size) {
    const float* q = (const float*)d_in[0];
    const float* k = (const float*)d_in[1];
    const float* v = (const float*)d_in[2];
    float* o = (float*)d_out;
    dim3 grid(NTILES / 2, B_);   // 16 balanced tile-pairs x 8 batches = 128 blocks
    fa_reg<<<grid, NT>>>(q, k, v, o);
}